// round 3
// baseline (speedup 1.0000x reference)
#include <cuda_runtime.h>
#include <math_constants.h>

#define NVEC   16384
#define KCODES 8192
#define CDIM   256
#define ZELEMS (16*256*32*32)   /* 4194304 */
#define NTILES 512              /* 32 n-rows each */
#define KCHUNKS 8               /* 1024 k each */
#define NUNITS (NTILES*KCHUNKS) /* 4096 */
#define GRID_P 304

__device__ float  g_zz[NVEC];
__device__ float  g_ee[KCODES];
__device__ int    g_idx[NVEC];
__device__ double g_loss;
__device__ int    g_unit;
__device__ float  g_pd[NTILES*KCHUNKS*32];
__device__ int    g_pk[NTILES*KCHUNKS*32];

typedef unsigned long long ull;

__device__ __forceinline__ void fma2(ull& d, ull a, ull b) {
    asm("fma.rn.f32x2 %0, %1, %2, %0;" : "+l"(d) : "l"(a), "l"(b));
}
__device__ __forceinline__ void unpack2(float& lo, float& hi, ull v) {
    unsigned a, b;
    asm("mov.b64 {%0, %1}, %2;" : "=r"(a), "=r"(b) : "l"(v));
    lo = __uint_as_float(a); hi = __uint_as_float(b);
}

// ---------------------------------------------------------------------------
// zz[n], ee[k] (sequential fp32 mul-add, matching reference); reset counters.
// z layout: [b][c][hw], b=n>>10, hw=n&1023
// ---------------------------------------------------------------------------
__global__ void prologue_kernel(const float* __restrict__ z,
                                const float* __restrict__ emb) {
    int i = blockIdx.x * blockDim.x + threadIdx.x;
    if (i == 0) { g_loss = 0.0; g_unit = 0; }
    if (i < NVEC) {
        int b = i >> 10, hw = i & 1023;
        const float* p = z + (size_t)b * 262144 + hw;
        float acc = 0.f;
        #pragma unroll 8
        for (int c = 0; c < CDIM; c++) {
            float v = p[(size_t)c * 1024];
            acc = __fadd_rn(acc, __fmul_rn(v, v));
        }
        g_zz[i] = acc;
    } else if (i < NVEC + KCODES) {
        int k = i - NVEC;
        const float* p = emb + (size_t)k * CDIM;
        float acc = 0.f;
        #pragma unroll 8
        for (int c = 0; c < CDIM; c++) {
            float v = p[c];
            acc = __fadd_rn(acc, __fmul_rn(v, v));
        }
        g_ee[k] = acc;
    }
}

// ---------------------------------------------------------------------------
// Persistent fused distance GEMM + per-chunk argmin.
// Unit = (ntile: 32 n-rows, kchunk: 1024 k). Dynamic queue over 4096 units.
// Packing: f32x2 lanes = adjacent k. e pairs free from natural [c][k'] smem
// (k' = k ^ ((c&15)<<2) swizzle); z dup panel zs[c][dup n] built once/unit.
// Thread (tx=t&31, ty=t>>5): 4 n (ty*4+i) x 8 k (4tx+{0..3}, 128+4tx+{0..3})
// per 256-k tile, kt = 4 tiles per unit. Per-lane accumulation c=0..255
// sequential fma -> bit-identical to verified R1/R2 path.
// ---------------------------------------------------------------------------
__global__ __launch_bounds__(256, 2)
void argmin_kernel(const float* __restrict__ z, const float* __restrict__ emb) {
    extern __shared__ float smem[];
    float* zs = smem;            // 16384 floats: [256 c][64 dup-n floats]
    float* es = smem + 16384;    // 2 x 4096 floats: [16 c][256 k'] each
    float* sd = es;              // scratch overlay after mainloop
    int*   si = (int*)(es + 1024);
    __shared__ int s_u;

    const int t  = threadIdx.x;
    const int tx = t & 31, ty = t >> 5;
    const int cq  = t & 3;       // loader: c-float4 index
    const int kkb = t >> 2;      // loader: k base (+64 per iter)

    int cur_ntile = -1;
    float zzr[4];

    for (;;) {
        if (t == 0) s_u = atomicAdd(&g_unit, 1);
        __syncthreads();
        const int u = s_u;
        if (u >= NUNITS) break;
        const int ntile  = u >> 3;
        const int kchunk = u & 7;

        if (ntile != cur_ntile) {
            cur_ntile = ntile;
            const int n0 = ntile * 32;
            const int b = n0 >> 10, hw0 = n0 & 1023;
            __syncthreads();   // everyone past zs reads of previous unit
            #pragma unroll
            for (int it = 0; it < 8; it++) {
                int idx = t + 256 * it;
                int c = idx >> 3, nq = idx & 7;
                float4 w = *(const float4*)&z[(size_t)b * 262144 + c * 1024 + hw0 + nq * 4];
                *(float4*)&zs[c * 64 + nq * 8]     = make_float4(w.x, w.x, w.y, w.y);
                *(float4*)&zs[c * 64 + nq * 8 + 4] = make_float4(w.z, w.z, w.w, w.w);
            }
            #pragma unroll
            for (int i = 0; i < 4; i++) zzr[i] = g_zz[n0 + ty * 4 + i];
        }

        float bestd[4]; int bestk[4];
        #pragma unroll
        for (int i = 0; i < 4; i++) { bestd[i] = CUDART_INF_F; bestk[i] = 0; }

        #pragma unroll 1
        for (int kt = 0; kt < 4; kt++) {
            const int kbase = kchunk * 1024 + kt * 256;

            ull acc[4][4];
            #pragma unroll
            for (int i = 0; i < 4; i++)
                #pragma unroll
                for (int p = 0; p < 4; p++) acc[i][p] = 0ull;

            float4 pre[4];
            // preload + store chunk 0
            #pragma unroll
            for (int it = 0; it < 4; it++) {
                int idx = t + 256 * it;
                int kk = (idx >> 2);
                int cql = idx & 3;
                pre[it] = *(const float4*)&emb[(size_t)(kbase + kk) * 256 + 4 * cql];
            }
            __syncthreads();   // es free (covers zs fill too)
            #pragma unroll
            for (int it = 0; it < 4; it++) {
                int idx = t + 256 * it;
                int kk = idx >> 2, cql = idx & 3;
                float* eb = es;
                float vj[4] = { pre[it].x, pre[it].y, pre[it].z, pre[it].w };
                #pragma unroll
                for (int j = 0; j < 4; j++) {
                    int cl = 4 * cql + j;
                    eb[cl * 256 + (kk ^ (cl << 2))] = vj[j];
                }
            }
            __syncthreads();

            #pragma unroll 1
            for (int ch = 0; ch < 16; ch++) {
                if (ch < 15) {
                    const int c0n = (ch + 1) * 16;
                    #pragma unroll
                    for (int it = 0; it < 4; it++) {
                        int idx = t + 256 * it;
                        int kk = idx >> 2, cql = idx & 3;
                        pre[it] = *(const float4*)&emb[(size_t)(kbase + kk) * 256 + c0n + 4 * cql];
                    }
                }
                const float* eb = es + (ch & 1) * 4096;

                #pragma unroll
                for (int c = 0; c < 16; c++) {
                    const int cg = ch * 16 + c;
                    const int swf = c << 2;   // (c&15)<<2, float-index XOR
                    ulonglong2 zA = *(const ulonglong2*)&zs[cg * 64 + ty * 8];
                    ulonglong2 zB = *(const ulonglong2*)&zs[cg * 64 + ty * 8 + 4];
                    ulonglong2 eA = *(const ulonglong2*)&eb[c * 256 + ((tx * 4) ^ swf)];
                    ulonglong2 eB = *(const ulonglong2*)&eb[c * 256 + ((128 + tx * 4) ^ swf)];
                    fma2(acc[0][0], zA.x, eA.x); fma2(acc[0][1], zA.x, eA.y);
                    fma2(acc[0][2], zA.x, eB.x); fma2(acc[0][3], zA.x, eB.y);
                    fma2(acc[1][0], zA.y, eA.x); fma2(acc[1][1], zA.y, eA.y);
                    fma2(acc[1][2], zA.y, eB.x); fma2(acc[1][3], zA.y, eB.y);
                    fma2(acc[2][0], zB.x, eA.x); fma2(acc[2][1], zB.x, eA.y);
                    fma2(acc[2][2], zB.x, eB.x); fma2(acc[2][3], zB.x, eB.y);
                    fma2(acc[3][0], zB.y, eA.x); fma2(acc[3][1], zB.y, eA.y);
                    fma2(acc[3][2], zB.y, eB.x); fma2(acc[3][3], zB.y, eB.y);
                }

                if (ch < 15) {
                    float* ebn = es + ((ch + 1) & 1) * 4096;
                    #pragma unroll
                    for (int it = 0; it < 4; it++) {
                        int idx = t + 256 * it;
                        int kk = idx >> 2, cql = idx & 3;
                        float vj[4] = { pre[it].x, pre[it].y, pre[it].z, pre[it].w };
                        #pragma unroll
                        for (int j = 0; j < 4; j++) {
                            int cl = 4 * cql + j;
                            ebn[cl * 256 + (kk ^ (cl << 2))] = vj[j];
                        }
                    }
                    __syncthreads();
                }
            }

            // epilogue: rounded distances, running argmin (k ascending)
            float4 eeA = *(const float4*)&g_ee[kbase + 4 * tx];
            float4 eeB = *(const float4*)&g_ee[kbase + 128 + 4 * tx];
            float eev[8] = { eeA.x, eeA.y, eeA.z, eeA.w, eeB.x, eeB.y, eeB.z, eeB.w };
            #pragma unroll
            for (int p = 0; p < 4; p++) {
                int klo = kbase + (p >> 1) * 128 + 4 * tx + (p & 1) * 2;
                float eel = eev[(p >> 1) * 4 + (p & 1) * 2];
                float eeh = eev[(p >> 1) * 4 + (p & 1) * 2 + 1];
                #pragma unroll
                for (int i = 0; i < 4; i++) {
                    float dlo, dhi;
                    unpack2(dlo, dhi, acc[i][p]);
                    float d0 = __fsub_rn(__fadd_rn(zzr[i], eel), __fmul_rn(2.0f, dlo));
                    float d1 = __fsub_rn(__fadd_rn(zzr[i], eeh), __fmul_rn(2.0f, dhi));
                    if (d0 < bestd[i]) { bestd[i] = d0; bestk[i] = klo; }
                    if (d1 < bestd[i]) { bestd[i] = d1; bestk[i] = klo + 1; }
                }
            }
        }

        // per-unit reduce across tx; write partials
        __syncthreads();   // es mainloop reads done -> scratch reuse
        #pragma unroll
        for (int i = 0; i < 4; i++) {
            sd[(ty * 4 + i) * 32 + tx] = bestd[i];
            si[(ty * 4 + i) * 32 + tx] = bestk[i];
        }
        __syncthreads();
        if (t < 32) {
            float bd = CUDART_INF_F; int bk = 0x7fffffff;
            #pragma unroll 4
            for (int x = 0; x < 32; x++) {
                float d = sd[t * 32 + x];
                int   k = si[t * 32 + x];
                if (d < bd || (d == bd && k < bk)) { bd = d; bk = k; }
            }
            g_pd[(ntile * 8 + kchunk) * 32 + t] = bd;
            g_pk[(ntile * 8 + kchunk) * 32 + t] = bk;
        }
        __syncthreads();   // scratch/es/s_u safe for next unit
    }
}

// ---------------------------------------------------------------------------
// Combine per-chunk partials: chunk ascending == k ascending; strict <
// replicates reference first-index argmin across the full K range.
// ---------------------------------------------------------------------------
__global__ void combine_kernel() {
    int n = blockIdx.x * 256 + threadIdx.x;
    if (n >= NVEC) return;
    int ntile = n >> 5, nl = n & 31;
    float bd = CUDART_INF_F; int bk = 0;
    #pragma unroll
    for (int ch = 0; ch < KCHUNKS; ch++) {
        float d = g_pd[(ntile * 8 + ch) * 32 + nl];
        int   k = g_pk[(ntile * 8 + ch) * 32 + nl];
        if (d < bd) { bd = d; bk = k; }
    }
    g_idx[n] = bk;
}

// ---------------------------------------------------------------------------
// out[o] = fl(z + fl(zq - z)) ; loss = sum fl(zq-z)^2 (double atomics)
// ---------------------------------------------------------------------------
__global__ void gather_kernel(const float* __restrict__ z,
                              const float* __restrict__ emb,
                              float* __restrict__ out) {
    int o = blockIdx.x * 256 + threadIdx.x;
    int rem = o & 262143;
    int b  = o >> 18;
    int c  = rem >> 10;
    int hw = rem & 1023;
    int n  = (b << 10) + hw;
    float zv = z[o];
    float q  = emb[(size_t)g_idx[n] * CDIM + c];
    float diff = __fsub_rn(q, zv);
    out[o] = __fadd_rn(zv, diff);
    float d2 = __fmul_rn(diff, diff);

    __shared__ float red[256];
    red[threadIdx.x] = d2;
    __syncthreads();
    for (int s = 128; s > 0; s >>= 1) {
        if (threadIdx.x < s) red[threadIdx.x] += red[threadIdx.x + s];
        __syncthreads();
    }
    if (threadIdx.x == 0) atomicAdd(&g_loss, (double)red[0]);
}

__global__ void tail_kernel(float* __restrict__ out, int out_size) {
    int i = blockIdx.x * 256 + threadIdx.x;
    if (i < NVEC && out_size >= ZELEMS + NVEC)
        out[ZELEMS + i] = (float)g_idx[i];
    if (i == 0 && out_size >= ZELEMS + NVEC + 1) {
        float m = (float)(g_loss / (double)ZELEMS);
        out[ZELEMS + NVEC] = __fadd_rn(m, __fmul_rn(0.25f, m)); // m + BETA*m
    }
}

// ---------------------------------------------------------------------------
extern "C" void kernel_launch(void* const* d_in, const int* in_sizes, int n_in,
                              void* d_out, int out_size) {
    const float* z   = (const float*)d_in[0];
    const float* emb = (const float*)d_in[1];
    float* out = (float*)d_out;

    cudaFuncSetAttribute(argmin_kernel,
                         cudaFuncAttributeMaxDynamicSharedMemorySize, 98304);

    prologue_kernel<<<(NVEC + KCODES + 255) / 256, 256>>>(z, emb);
    argmin_kernel<<<GRID_P, 256, 98304>>>(z, emb);
    combine_kernel<<<NVEC / 256, 256>>>();
    gather_kernel<<<ZELEMS / 256, 256>>>(z, emb, out);
    tail_kernel<<<(NVEC + 255) / 256, 256>>>(out, out_size);
}